// round 10
// baseline (speedup 1.0000x reference)
#include <cuda_runtime.h>
#include <cuda_fp16.h>
#include <cstdint>

#define BB 2
#define DD 160
#define HH 192
#define WW 160
#define HW (HH*WW)               // 30720
#define DHW (DD*HH*WW)           // 4,915,200
#define NVOX (BB*DD*HH*WW)       // 9,830,400
#define NV4 (NVOX/4)             // 2,457,600
#define INV_WIN3 (1.0f/729.0f)

// ---------------- K1: stats + H box-sum (fp16 ring + prefetch) ----------
#define SEG_H1 12
#define SEGLEN_H1 (HH/SEG_H1)    // 16 (multiple of 8 -> compile-time ring slots)
#define COLS4 (BB*DD*WW/4)       // 12800 float4 columns
#define K1_THREADS (COLS4*SEG_H1)  // 153600
#define K1_BLK 256

// ---------------- K2: D-roll + W-roll + cc + reduce ----------------
#define ROWS2 4
#define SEG_D2 10
#define SEGLEN_D2 (DD/SEG_D2)    // 16
#define HTILES (HH/ROWS2)        // 48
#define K2_BLOCKS (BB*HTILES*SEG_D2)   // 960
#define K2_THREADS 160           // 4 rows x 40 float4-lanes
#define SMROW 42                 // float4s per padded row (1 pad + 40 + 1 pad)
#define SMBUF (5*ROWS2*SMROW)    // 840 float4 per buffer

// Packed fp16 H-summed stats (written once by K1, read by K2). ~98 MB total.
__device__ uint4 g_ab[NV4];      // ch0(I),  ch1(J)   : 8 halves
__device__ uint4 g_cd[NV4];      // ch2(I2), ch3(J2)  : 8 halves
__device__ uint2 g_e [NV4];      // ch4(IJ)           : 4 halves
__device__ double g_part[K2_BLOCKS];
__device__ int g_sem;            // self-resetting (0 at start of every replay)

__device__ __forceinline__ unsigned int pack2(float a, float b) {
    __half2 h = __floats2half2_rn(a, b);
    return *(unsigned int*)&h;
}
__device__ __forceinline__ float2 unpack2(unsigned int u) {
    __half2 h = *(__half2*)&u;
    return __half22float2(h);
}
__device__ __forceinline__ uint2 packf4(float4 v) {
    uint2 r; r.x = pack2(v.x, v.y); r.y = pack2(v.z, v.w); return r;
}
__device__ __forceinline__ float4 unpackf4(uint2 u) {
    float2 a = unpack2(u.x), b = unpack2(u.y);
    return make_float4(a.x, a.y, b.x, b.y);
}

__device__ __forceinline__ void acc_add(float4 s[5], float4 i, float4 j) {
    s[0].x+=i.x; s[0].y+=i.y; s[0].z+=i.z; s[0].w+=i.w;
    s[1].x+=j.x; s[1].y+=j.y; s[1].z+=j.z; s[1].w+=j.w;
    s[2].x+=i.x*i.x; s[2].y+=i.y*i.y; s[2].z+=i.z*i.z; s[2].w+=i.w*i.w;
    s[3].x+=j.x*j.x; s[3].y+=j.y*j.y; s[3].z+=j.z*j.z; s[3].w+=j.w*j.w;
    s[4].x+=i.x*j.x; s[4].y+=i.y*j.y; s[4].z+=i.z*j.z; s[4].w+=i.w*j.w;
}
__device__ __forceinline__ void acc_sub(float4 s[5], float4 i, float4 j) {
    s[0].x-=i.x; s[0].y-=i.y; s[0].z-=i.z; s[0].w-=i.w;
    s[1].x-=j.x; s[1].y-=j.y; s[1].z-=j.z; s[1].w-=j.w;
    s[2].x-=i.x*i.x; s[2].y-=i.y*i.y; s[2].z-=i.z*i.z; s[2].w-=i.w*i.w;
    s[3].x-=j.x*j.x; s[3].y-=j.y*j.y; s[3].z-=j.z*j.z; s[3].w-=j.w*j.w;
    s[4].x-=i.x*j.x; s[4].y-=i.y*j.y; s[4].z-=i.z*j.z; s[4].w-=i.w*j.w;
}

// ===========================================================================
// K1: thread = float4 column. Inputs rounded to fp16 at load; ring stores the
// PACKED rounded rows (32 regs), so rolling add/sub cancels exactly. Next
// step's loads prefetched before current accumulation chain (MLP 4).
// ===========================================================================
__global__ __launch_bounds__(K1_BLK) void stats_h_kernel(
    const float* __restrict__ I, const float* __restrict__ J) {
    int tid = blockIdx.x * K1_BLK + threadIdx.x;
    if (tid >= K1_THREADS) return;
    int col4 = tid % COLS4;
    int seg  = tid / COLS4;
    int b    = col4 / (DD * WW / 4);
    int rest = col4 % (DD * WW / 4);
    int d    = rest / (WW / 4);
    int w4   = rest % (WW / 4);
    const size_t base = (size_t)b * DHW + (size_t)d * HW + (size_t)w4 * 4;
    const int h0 = seg * SEGLEN_H1;   // multiple of 16

    uint2 ringI[8], ringJ[8];
    float4 s[5];
    #pragma unroll
    for (int c = 0; c < 5; ++c) s[c] = make_float4(0.f,0.f,0.f,0.f);

    #pragma unroll
    for (int k = 0; k < 8; ++k) {
        int h = h0 - 4 + k;
        float4 i = make_float4(0.f,0.f,0.f,0.f), j = i;
        if (h >= 0 && h < HH) {
            i = __ldcs((const float4*)&I[base + (size_t)h * WW]);
            j = __ldcs((const float4*)&J[base + (size_t)h * WW]);
        }
        uint2 ip = packf4(i), jp = packf4(j);
        ringI[(k + 4) & 7] = ip;
        ringJ[(k + 4) & 7] = jp;
        acc_add(s, unpackf4(ip), unpackf4(jp));
    }

    // Prefetch the row for the first main step (h0+4).
    float4 pi = make_float4(0.f,0.f,0.f,0.f), pj = pi;
    if (h0 + 4 < HH) {
        pi = __ldcs((const float4*)&I[base + (size_t)(h0 + 4) * WW]);
        pj = __ldcs((const float4*)&J[base + (size_t)(h0 + 4) * WW]);
    }

    for (int hb = h0; hb < h0 + SEGLEN_H1; hb += 8) {
        #pragma unroll
        for (int u = 0; u < 8; ++u) {
            const int slot = (u + 4) & 7;     // == (hb+u+4)&7 since hb%8==0
            int h  = hb + u;
            uint2 nip = packf4(pi), njp = packf4(pj);
            // prefetch next step's row (h+5) — independent, issues early
            int hn = h + 5;
            float4 npi = make_float4(0.f,0.f,0.f,0.f), npj = npi;
            if (hn < HH) {
                npi = __ldcs((const float4*)&I[base + (size_t)hn * WW]);
                npj = __ldcs((const float4*)&J[base + (size_t)hn * WW]);
            }
            acc_add(s, unpackf4(nip), unpackf4(njp));  // window now [h-4,h+4]
            size_t o4 = (base + (size_t)h * WW) >> 2;
            uint4 pab = make_uint4(pack2(s[0].x, s[0].y), pack2(s[0].z, s[0].w),
                                   pack2(s[1].x, s[1].y), pack2(s[1].z, s[1].w));
            uint4 pcd = make_uint4(pack2(s[2].x, s[2].y), pack2(s[2].z, s[2].w),
                                   pack2(s[3].x, s[3].y), pack2(s[3].z, s[3].w));
            uint2 pe  = make_uint2(pack2(s[4].x, s[4].y), pack2(s[4].z, s[4].w));
            __stcs(&g_ab[o4], pab);
            __stcs(&g_cd[o4], pcd);
            __stcs(&g_e [o4], pe);
            acc_sub(s, unpackf4(ringI[slot]), unpackf4(ringJ[slot]));  // exact
            ringI[slot] = nip; ringJ[slot] = njp;
            pi = npi; pj = npj;
        }
    }
}

// ===========================================================================
// K2: rolling D box-sum per float4 column; fused diff update (HSUB2 on packed
// fp16), double-buffered smem stage (one barrier/step), 9-wide W windows + cc,
// global reduction with fused finalize.
// Recurrence: window(dd) = window(dd-1) + row(dd+4) - row(dd-5), so the
// prime sum must cover [max(0, d0-5), d0+3].
// ===========================================================================
__device__ __forceinline__ float cc1(float s0, float s1, float s2, float s3,
                                     float s4) {
    float cross = fmaf(-s0 * INV_WIN3, s1, s4);
    float Ivar  = fmaf(-s0 * INV_WIN3, s0, s2);
    float Jvar  = fmaf(-s1 * INV_WIN3, s1, s3);
    return __fdividef(cross * cross, fmaf(Ivar, Jvar, 1e-5f));
}

__device__ __forceinline__ void load_add(float4 s[5], size_t o4, float sgn) {
    uint4 vab = __ldcg(&g_ab[o4]);
    uint4 vcd = __ldcg(&g_cd[o4]);
    uint2 ve  = __ldcg(&g_e [o4]);
    float2 p;
    p = unpack2(vab.x); s[0].x += sgn*p.x; s[0].y += sgn*p.y;
    p = unpack2(vab.y); s[0].z += sgn*p.x; s[0].w += sgn*p.y;
    p = unpack2(vab.z); s[1].x += sgn*p.x; s[1].y += sgn*p.y;
    p = unpack2(vab.w); s[1].z += sgn*p.x; s[1].w += sgn*p.y;
    p = unpack2(vcd.x); s[2].x += sgn*p.x; s[2].y += sgn*p.y;
    p = unpack2(vcd.y); s[2].z += sgn*p.x; s[2].w += sgn*p.y;
    p = unpack2(vcd.z); s[3].x += sgn*p.x; s[3].y += sgn*p.y;
    p = unpack2(vcd.w); s[3].z += sgn*p.x; s[3].w += sgn*p.y;
    p = unpack2(ve.x);  s[4].x += sgn*p.x; s[4].y += sgn*p.y;
    p = unpack2(ve.y);  s[4].z += sgn*p.x; s[4].w += sgn*p.y;
}

__device__ __forceinline__ void hdiff_add(float& x, float& y,
                                          unsigned int a, unsigned int b) {
    __half2 ha = *(__half2*)&a, hb = *(__half2*)&b;
    __half2 d = __hsub2(ha, hb);
    float2 p = __half22float2(d);
    x += p.x; y += p.y;
}

// s += row(oa) - row(os), diff computed in packed fp16 (HSUB2): ~30 fewer
// instructions than separate add+sub streams.
__device__ __forceinline__ void load_diff_add(float4 s[5], size_t oa, size_t os) {
    uint4 Aab = __ldcg(&g_ab[oa]); uint4 Bab = __ldcs(&g_ab[os]);
    uint4 Acd = __ldcg(&g_cd[oa]); uint4 Bcd = __ldcs(&g_cd[os]);
    uint2 Ae  = __ldcg(&g_e [oa]); uint2 Be  = __ldcs(&g_e [os]);
    hdiff_add(s[0].x, s[0].y, Aab.x, Bab.x);
    hdiff_add(s[0].z, s[0].w, Aab.y, Bab.y);
    hdiff_add(s[1].x, s[1].y, Aab.z, Bab.z);
    hdiff_add(s[1].z, s[1].w, Aab.w, Bab.w);
    hdiff_add(s[2].x, s[2].y, Acd.x, Bcd.x);
    hdiff_add(s[2].z, s[2].w, Acd.y, Bcd.y);
    hdiff_add(s[3].x, s[3].y, Acd.z, Bcd.z);
    hdiff_add(s[3].z, s[3].w, Acd.w, Bcd.w);
    hdiff_add(s[4].x, s[4].y, Ae.x,  Be.x);
    hdiff_add(s[4].z, s[4].w, Ae.y,  Be.y);
}

__global__ __launch_bounds__(K2_THREADS) void dwc_kernel(float* __restrict__ out) {
    __shared__ float4 sm[2][SMBUF];            // double-buffered, 26,880 B
    __shared__ double wsum[K2_THREADS / 32];
    __shared__ bool is_last;

    int bx   = blockIdx.x;
    int dseg = bx % SEG_D2;
    int rest = bx / SEG_D2;
    int htile = rest % HTILES;
    int b     = rest / HTILES;
    int h0 = htile * ROWS2;
    int tid = threadIdx.x;
    int r  = tid / 40;
    int wi = tid % 40;

    for (int i = tid; i < 2 * SMBUF; i += K2_THREADS)
        sm[0][i] = make_float4(0.f, 0.f, 0.f, 0.f);   // zero both (pads!)

    const size_t colbase = (size_t)b * DHW + (size_t)(h0 + r) * WW + wi * 4;
    int d0 = dseg * SEGLEN_D2;

    float4 s[5];
    #pragma unroll
    for (int c = 0; c < 5; ++c) s[c] = make_float4(0.f, 0.f, 0.f, 0.f);

    // Prime: s = sum rows [max(0, d0-5), d0+3]  (pre-window for the
    // start-of-step recurrence: first step adds d0+4 and removes d0-5).
    int dp = d0 - 5 > 0 ? d0 - 5 : 0;
    for (int d = dp; d < d0 + 4; ++d)
        load_add(s, (colbase + (size_t)d * HW) >> 2, 1.f);
    __syncthreads();   // pads zeroed before first stage

    float acc = 0.f;
    int pb = 0;
    for (int dd = d0; dd < d0 + SEGLEN_D2; ++dd) {
        // Update at START of step: add row dd+4, remove row dd-5.
        int da = dd + 4, ds = dd - 5;
        if (da < DD && ds >= 0) {
            load_diff_add(s, (colbase + (size_t)da * HW) >> 2,
                             (colbase + (size_t)ds * HW) >> 2);
        } else {
            if (da < DD) load_add(s, (colbase + (size_t)da * HW) >> 2,  1.f);
            if (ds >= 0) load_add(s, (colbase + (size_t)ds * HW) >> 2, -1.f);
        }

        float4* buf = sm[pb];
        #pragma unroll
        for (int c = 0; c < 5; ++c)
            buf[(c * ROWS2 + r) * SMROW + 1 + wi] = s[c];
        __syncthreads();   // the ONLY barrier per step (double-buffered)

        float win[5][4];
        #pragma unroll
        for (int c = 0; c < 5; ++c) {
            int rb = (c * ROWS2 + r) * SMROW + wi;
            float4 a0 = buf[rb], a1 = s[c], a2 = buf[rb + 2];
            float f0=a0.x,f1=a0.y,f2=a0.z,f3=a0.w;
            float f4_=a1.x,f5=a1.y,f6=a1.z,f7=a1.w;
            float f8=a2.x,f9=a2.y,f10=a2.z,f11=a2.w;
            float t = f0+f1+f2+f3+f4_+f5+f6+f7+f8;
            win[c][0] = t;
            t += f9  - f0; win[c][1] = t;
            t += f10 - f1; win[c][2] = t;
            t += f11 - f2; win[c][3] = t;
        }
        #pragma unroll
        for (int k = 0; k < 4; ++k)
            acc += cc1(win[0][k], win[1][k], win[2][k], win[3][k], win[4][k]);
        pb ^= 1;
    }

    #pragma unroll
    for (int off = 16; off; off >>= 1)
        acc += __shfl_down_sync(0xffffffffu, acc, off);
    int lane = tid & 31, wid = tid >> 5;
    if (lane == 0) wsum[wid] = (double)acc;
    __syncthreads();

    if (tid == 0) {
        double t = 0.0;
        #pragma unroll
        for (int i = 0; i < K2_THREADS / 32; ++i) t += wsum[i];
        g_part[bx] = t;
        __threadfence();
        int v = atomicAdd(&g_sem, 1);
        is_last = (v == gridDim.x - 1);
    }
    __syncthreads();

    if (is_last) {
        __threadfence();
        double t = 0.0;
        for (int i = tid; i < K2_BLOCKS; i += K2_THREADS) t += g_part[i];
        #pragma unroll
        for (int off = 16; off; off >>= 1)
            t += __shfl_down_sync(0xffffffffu, t, off);
        if (lane == 0) wsum[wid] = t;
        __syncthreads();
        if (tid == 0) {
            double tot = 0.0;
            #pragma unroll
            for (int i = 0; i < K2_THREADS / 32; ++i) tot += wsum[i];
            out[0] = (float)(tot / (double)NVOX);
            g_sem = 0;   // reset for next graph replay
        }
    }
}

extern "C" void kernel_launch(void* const* d_in, const int* in_sizes, int n_in,
                              void* d_out, int out_size) {
    const float* I = (const float*)d_in[0];  // predicted
    const float* J = (const float*)d_in[1];  // target

    stats_h_kernel<<<(K1_THREADS + K1_BLK - 1) / K1_BLK, K1_BLK>>>(I, J);
    dwc_kernel<<<K2_BLOCKS, K2_THREADS>>>((float*)d_out);
}

// round 11
// speedup vs baseline: 1.0510x; 1.0510x over previous
#include <cuda_runtime.h>
#include <cuda_fp16.h>
#include <cstdint>

#define BB 2
#define DD 160
#define HH 192
#define WW 160
#define HW (HH*WW)               // 30720
#define DHW (DD*HH*WW)           // 4,915,200
#define NVOX (BB*DD*HH*WW)       // 9,830,400
#define NV4 (NVOX/4)             // 2,457,600
#define INV_WIN3 (1.0f/729.0f)

// ---------------- K1: stats + H box-sum (fp16 ring + prefetch) ----------
#define SEG_H1 12
#define SEGLEN_H1 (HH/SEG_H1)    // 16 (multiple of 8 -> compile-time ring slots)
#define COLS4 (BB*DD*WW/4)       // 12800 float4 columns
#define K1_THREADS (COLS4*SEG_H1)  // 153600
#define K1_BLK 256

// ---------------- K2: D-roll + W-roll + cc + reduce ----------------
#define ROWS2 4
#define SEG_D2 10
#define SEGLEN_D2 (DD/SEG_D2)    // 16
#define HTILES (HH/ROWS2)        // 48
#define K2_BLOCKS (BB*HTILES*SEG_D2)   // 960
#define K2_THREADS 160           // 4 rows x 40 float4-lanes
#define SMROW 42                 // slots per padded row (1 pad + 40 + 1 pad)
#define SMN (ROWS2*SMROW)        // 168 slots per buffer

// Packed fp16 H-summed stats (written once by K1, read by K2). ~98 MB total.
__device__ uint4 g_ab[NV4];      // ch0(I),  ch1(J)   : 8 halves
__device__ uint4 g_cd[NV4];      // ch2(I2), ch3(J2)  : 8 halves
__device__ uint2 g_e [NV4];      // ch4(IJ)           : 4 halves
__device__ double g_part[K2_BLOCKS];
__device__ int g_sem;            // self-resetting (0 at start of every replay)

__device__ __forceinline__ unsigned int pack2(float a, float b) {
    __half2 h = __floats2half2_rn(a, b);
    return *(unsigned int*)&h;
}
__device__ __forceinline__ float2 unpack2(unsigned int u) {
    __half2 h = *(__half2*)&u;
    return __half22float2(h);
}
__device__ __forceinline__ __half2 u2h(unsigned int u) {
    return *(__half2*)&u;
}
__device__ __forceinline__ uint2 packf4(float4 v) {
    uint2 r; r.x = pack2(v.x, v.y); r.y = pack2(v.z, v.w); return r;
}
__device__ __forceinline__ float4 unpackf4(uint2 u) {
    float2 a = unpack2(u.x), b = unpack2(u.y);
    return make_float4(a.x, a.y, b.x, b.y);
}

__device__ __forceinline__ void acc_add(float4 s[5], float4 i, float4 j) {
    s[0].x+=i.x; s[0].y+=i.y; s[0].z+=i.z; s[0].w+=i.w;
    s[1].x+=j.x; s[1].y+=j.y; s[1].z+=j.z; s[1].w+=j.w;
    s[2].x+=i.x*i.x; s[2].y+=i.y*i.y; s[2].z+=i.z*i.z; s[2].w+=i.w*i.w;
    s[3].x+=j.x*j.x; s[3].y+=j.y*j.y; s[3].z+=j.z*j.z; s[3].w+=j.w*j.w;
    s[4].x+=i.x*j.x; s[4].y+=i.y*j.y; s[4].z+=i.z*j.z; s[4].w+=i.w*j.w;
}
__device__ __forceinline__ void acc_sub(float4 s[5], float4 i, float4 j) {
    s[0].x-=i.x; s[0].y-=i.y; s[0].z-=i.z; s[0].w-=i.w;
    s[1].x-=j.x; s[1].y-=j.y; s[1].z-=j.z; s[1].w-=j.w;
    s[2].x-=i.x*i.x; s[2].y-=i.y*i.y; s[2].z-=i.z*i.z; s[2].w-=i.w*i.w;
    s[3].x-=j.x*j.x; s[3].y-=j.y*j.y; s[3].z-=j.z*j.z; s[3].w-=j.w*j.w;
    s[4].x-=i.x*j.x; s[4].y-=i.y*j.y; s[4].z-=i.z*j.z; s[4].w-=i.w*j.w;
}

// ===========================================================================
// K1: thread = float4 column. Inputs rounded to fp16 at load; ring stores the
// PACKED rounded rows (32 regs), so rolling add/sub cancels exactly. Next
// step's loads prefetched before current accumulation chain.
// ===========================================================================
__global__ __launch_bounds__(K1_BLK) void stats_h_kernel(
    const float* __restrict__ I, const float* __restrict__ J) {
    int tid = blockIdx.x * K1_BLK + threadIdx.x;
    if (tid >= K1_THREADS) return;
    int col4 = tid % COLS4;
    int seg  = tid / COLS4;
    int b    = col4 / (DD * WW / 4);
    int rest = col4 % (DD * WW / 4);
    int d    = rest / (WW / 4);
    int w4   = rest % (WW / 4);
    const size_t base = (size_t)b * DHW + (size_t)d * HW + (size_t)w4 * 4;
    const int h0 = seg * SEGLEN_H1;   // multiple of 16

    uint2 ringI[8], ringJ[8];
    float4 s[5];
    #pragma unroll
    for (int c = 0; c < 5; ++c) s[c] = make_float4(0.f,0.f,0.f,0.f);

    #pragma unroll
    for (int k = 0; k < 8; ++k) {
        int h = h0 - 4 + k;
        float4 i = make_float4(0.f,0.f,0.f,0.f), j = i;
        if (h >= 0 && h < HH) {
            i = __ldcs((const float4*)&I[base + (size_t)h * WW]);
            j = __ldcs((const float4*)&J[base + (size_t)h * WW]);
        }
        uint2 ip = packf4(i), jp = packf4(j);
        ringI[(k + 4) & 7] = ip;
        ringJ[(k + 4) & 7] = jp;
        acc_add(s, unpackf4(ip), unpackf4(jp));
    }

    // Prefetch the row for the first main step (h0+4).
    float4 pi = make_float4(0.f,0.f,0.f,0.f), pj = pi;
    if (h0 + 4 < HH) {
        pi = __ldcs((const float4*)&I[base + (size_t)(h0 + 4) * WW]);
        pj = __ldcs((const float4*)&J[base + (size_t)(h0 + 4) * WW]);
    }

    for (int hb = h0; hb < h0 + SEGLEN_H1; hb += 8) {
        #pragma unroll
        for (int u = 0; u < 8; ++u) {
            const int slot = (u + 4) & 7;     // == (hb+u+4)&7 since hb%8==0
            int h  = hb + u;
            uint2 nip = packf4(pi), njp = packf4(pj);
            // prefetch next step's row (h+5) — independent, issues early
            int hn = h + 5;
            float4 npi = make_float4(0.f,0.f,0.f,0.f), npj = npi;
            if (hn < HH) {
                npi = __ldcs((const float4*)&I[base + (size_t)hn * WW]);
                npj = __ldcs((const float4*)&J[base + (size_t)hn * WW]);
            }
            acc_add(s, unpackf4(nip), unpackf4(njp));  // window now [h-4,h+4]
            size_t o4 = (base + (size_t)h * WW) >> 2;
            uint4 pab = make_uint4(pack2(s[0].x, s[0].y), pack2(s[0].z, s[0].w),
                                   pack2(s[1].x, s[1].y), pack2(s[1].z, s[1].w));
            uint4 pcd = make_uint4(pack2(s[2].x, s[2].y), pack2(s[2].z, s[2].w),
                                   pack2(s[3].x, s[3].y), pack2(s[3].z, s[3].w));
            uint2 pe  = make_uint2(pack2(s[4].x, s[4].y), pack2(s[4].z, s[4].w));
            __stcs(&g_ab[o4], pab);
            __stcs(&g_cd[o4], pcd);
            __stcs(&g_e [o4], pe);
            acc_sub(s, unpackf4(ringI[slot]), unpackf4(ringJ[slot]));  // exact
            ringI[slot] = nip; ringJ[slot] = njp;
            pi = npi; pj = npj;
        }
    }
}

// ===========================================================================
// K2: rolling D box-sum per float4 column (fp32 accum, fused HSUB2 diff);
// W exchange staged as PACKED half2 channel-pairs ({s0,s1},{s2,s3} uint4,
// s4 fp32), windows for ch0-3 computed 2-channels-per-op with HADD2/HSUB2.
// Recurrence: window(dd) = window(dd-1) + row(dd+4) - row(dd-5); prime
// covers [max(0, d0-5), d0+3].
// ===========================================================================
__device__ __forceinline__ float cc1(float s0, float s1, float s2, float s3,
                                     float s4) {
    float cross = fmaf(-s0 * INV_WIN3, s1, s4);
    float Ivar  = fmaf(-s0 * INV_WIN3, s0, s2);
    float Jvar  = fmaf(-s1 * INV_WIN3, s1, s3);
    return __fdividef(cross * cross, fmaf(Ivar, Jvar, 1e-5f));
}

__device__ __forceinline__ void load_add(float4 s[5], size_t o4, float sgn) {
    uint4 vab = __ldcg(&g_ab[o4]);
    uint4 vcd = __ldcg(&g_cd[o4]);
    uint2 ve  = __ldcg(&g_e [o4]);
    float2 p;
    p = unpack2(vab.x); s[0].x += sgn*p.x; s[0].y += sgn*p.y;
    p = unpack2(vab.y); s[0].z += sgn*p.x; s[0].w += sgn*p.y;
    p = unpack2(vab.z); s[1].x += sgn*p.x; s[1].y += sgn*p.y;
    p = unpack2(vab.w); s[1].z += sgn*p.x; s[1].w += sgn*p.y;
    p = unpack2(vcd.x); s[2].x += sgn*p.x; s[2].y += sgn*p.y;
    p = unpack2(vcd.y); s[2].z += sgn*p.x; s[2].w += sgn*p.y;
    p = unpack2(vcd.z); s[3].x += sgn*p.x; s[3].y += sgn*p.y;
    p = unpack2(vcd.w); s[3].z += sgn*p.x; s[3].w += sgn*p.y;
    p = unpack2(ve.x);  s[4].x += sgn*p.x; s[4].y += sgn*p.y;
    p = unpack2(ve.y);  s[4].z += sgn*p.x; s[4].w += sgn*p.y;
}

__device__ __forceinline__ void hdiff_add(float& x, float& y,
                                          unsigned int a, unsigned int b) {
    __half2 d = __hsub2(u2h(a), u2h(b));
    float2 p = __half22float2(d);
    x += p.x; y += p.y;
}

// s += row(oa) - row(os), diff computed in packed fp16 (HSUB2).
__device__ __forceinline__ void load_diff_add(float4 s[5], size_t oa, size_t os) {
    uint4 Aab = __ldcg(&g_ab[oa]); uint4 Bab = __ldcs(&g_ab[os]);
    uint4 Acd = __ldcg(&g_cd[oa]); uint4 Bcd = __ldcs(&g_cd[os]);
    uint2 Ae  = __ldcg(&g_e [oa]); uint2 Be  = __ldcs(&g_e [os]);
    hdiff_add(s[0].x, s[0].y, Aab.x, Bab.x);
    hdiff_add(s[0].z, s[0].w, Aab.y, Bab.y);
    hdiff_add(s[1].x, s[1].y, Aab.z, Bab.z);
    hdiff_add(s[1].z, s[1].w, Aab.w, Bab.w);
    hdiff_add(s[2].x, s[2].y, Acd.x, Bcd.x);
    hdiff_add(s[2].z, s[2].w, Acd.y, Bcd.y);
    hdiff_add(s[3].x, s[3].y, Acd.z, Bcd.z);
    hdiff_add(s[3].z, s[3].w, Acd.w, Bcd.w);
    hdiff_add(s[4].x, s[4].y, Ae.x,  Be.x);
    hdiff_add(s[4].z, s[4].w, Ae.y,  Be.y);
}

// 9-wide windows over 12 half2 values (L=4, own=4, R=4), 2 channels per op.
__device__ __forceinline__ void win_h2(__half2 win[4], uint4 L, uint4 own,
                                       uint4 R) {
    __half2 h0 = u2h(L.x),  h1 = u2h(L.y),  h2 = u2h(L.z),  h3 = u2h(L.w);
    __half2 h4 = u2h(own.x),h5 = u2h(own.y),h6 = u2h(own.z),h7 = u2h(own.w);
    __half2 h8 = u2h(R.x),  h9 = u2h(R.y),  h10= u2h(R.z),  h11= u2h(R.w);
    __half2 t = __hadd2(__hadd2(__hadd2(h0, h1), __hadd2(h2, h3)),
                        __hadd2(__hadd2(h4, h5), __hadd2(__hadd2(h6, h7), h8)));
    win[0] = t;
    t = __hadd2(t, __hsub2(h9,  h0)); win[1] = t;
    t = __hadd2(t, __hsub2(h10, h1)); win[2] = t;
    t = __hadd2(t, __hsub2(h11, h2)); win[3] = t;
}

__global__ __launch_bounds__(K2_THREADS) void dwc_kernel(float* __restrict__ out) {
    __shared__ uint4  smAB[2][SMN];            // {s0,s1} half2 x4 per slot
    __shared__ uint4  smCD[2][SMN];            // {s2,s3} half2 x4 per slot
    __shared__ float4 smE [2][SMN];            // s4 fp32
    __shared__ double wsum[K2_THREADS / 32];
    __shared__ bool is_last;

    int bx   = blockIdx.x;
    int dseg = bx % SEG_D2;
    int rest = bx / SEG_D2;
    int htile = rest % HTILES;
    int b     = rest / HTILES;
    int h0 = htile * ROWS2;
    int tid = threadIdx.x;
    int r  = tid / 40;
    int wi = tid % 40;

    // zero everything (pads included; zero bits == zero halves)
    for (int i = tid; i < 2 * SMN; i += K2_THREADS) {
        smAB[0][i] = make_uint4(0u, 0u, 0u, 0u);
        smCD[0][i] = make_uint4(0u, 0u, 0u, 0u);
        smE [0][i] = make_float4(0.f, 0.f, 0.f, 0.f);
    }

    const size_t colbase = (size_t)b * DHW + (size_t)(h0 + r) * WW + wi * 4;
    int d0 = dseg * SEGLEN_D2;

    float4 s[5];
    #pragma unroll
    for (int c = 0; c < 5; ++c) s[c] = make_float4(0.f, 0.f, 0.f, 0.f);

    // Prime: s = sum rows [max(0, d0-5), d0+3].
    int dp = d0 - 5 > 0 ? d0 - 5 : 0;
    for (int d = dp; d < d0 + 4; ++d)
        load_add(s, (colbase + (size_t)d * HW) >> 2, 1.f);
    __syncthreads();   // pads zeroed before first stage

    const int rb = r * SMROW + wi;   // left slot; own = rb+1; right = rb+2
    float acc = 0.f;
    int pb = 0;
    for (int dd = d0; dd < d0 + SEGLEN_D2; ++dd) {
        int da = dd + 4, ds = dd - 5;
        if (da < DD && ds >= 0) {
            load_diff_add(s, (colbase + (size_t)da * HW) >> 2,
                             (colbase + (size_t)ds * HW) >> 2);
        } else {
            if (da < DD) load_add(s, (colbase + (size_t)da * HW) >> 2,  1.f);
            if (ds >= 0) load_add(s, (colbase + (size_t)ds * HW) >> 2, -1.f);
        }

        // pack channel pairs (fp16) and stage
        uint4 abp = make_uint4(pack2(s[0].x, s[1].x), pack2(s[0].y, s[1].y),
                               pack2(s[0].z, s[1].z), pack2(s[0].w, s[1].w));
        uint4 cdp = make_uint4(pack2(s[2].x, s[3].x), pack2(s[2].y, s[3].y),
                               pack2(s[2].z, s[3].z), pack2(s[2].w, s[3].w));
        smAB[pb][rb + 1] = abp;
        smCD[pb][rb + 1] = cdp;
        smE [pb][rb + 1] = s[4];
        __syncthreads();   // the ONLY barrier per step (double-buffered)

        __half2 wab[4], wcd[4];
        win_h2(wab, smAB[pb][rb], abp, smAB[pb][rb + 2]);
        win_h2(wcd, smCD[pb][rb], cdp, smCD[pb][rb + 2]);

        float wine[4];
        {
            float4 a0 = smE[pb][rb], a2 = smE[pb][rb + 2];
            float f0=a0.x,f1=a0.y,f2=a0.z,f3=a0.w;
            float f4_=s[4].x,f5=s[4].y,f6=s[4].z,f7=s[4].w;
            float f8=a2.x,f9=a2.y,f10=a2.z,f11=a2.w;
            float t = f0+f1+f2+f3+f4_+f5+f6+f7+f8;
            wine[0] = t;
            t += f9  - f0; wine[1] = t;
            t += f10 - f1; wine[2] = t;
            t += f11 - f2; wine[3] = t;
        }
        #pragma unroll
        for (int k = 0; k < 4; ++k) {
            float2 ab = __half22float2(wab[k]);
            float2 cd = __half22float2(wcd[k]);
            acc += cc1(ab.x, ab.y, cd.x, cd.y, wine[k]);
        }
        pb ^= 1;
    }

    #pragma unroll
    for (int off = 16; off; off >>= 1)
        acc += __shfl_down_sync(0xffffffffu, acc, off);
    int lane = tid & 31, wid = tid >> 5;
    if (lane == 0) wsum[wid] = (double)acc;
    __syncthreads();

    if (tid == 0) {
        double t = 0.0;
        #pragma unroll
        for (int i = 0; i < K2_THREADS / 32; ++i) t += wsum[i];
        g_part[bx] = t;
        __threadfence();
        int v = atomicAdd(&g_sem, 1);
        is_last = (v == gridDim.x - 1);
    }
    __syncthreads();

    if (is_last) {
        __threadfence();
        double t = 0.0;
        for (int i = tid; i < K2_BLOCKS; i += K2_THREADS) t += g_part[i];
        #pragma unroll
        for (int off = 16; off; off >>= 1)
            t += __shfl_down_sync(0xffffffffu, t, off);
        if (lane == 0) wsum[wid] = t;
        __syncthreads();
        if (tid == 0) {
            double tot = 0.0;
            #pragma unroll
            for (int i = 0; i < K2_THREADS / 32; ++i) tot += wsum[i];
            out[0] = (float)(tot / (double)NVOX);
            g_sem = 0;   // reset for next graph replay
        }
    }
}

extern "C" void kernel_launch(void* const* d_in, const int* in_sizes, int n_in,
                              void* d_out, int out_size) {
    const float* I = (const float*)d_in[0];  // predicted
    const float* J = (const float*)d_in[1];  // target

    stats_h_kernel<<<(K1_THREADS + K1_BLK - 1) / K1_BLK, K1_BLK>>>(I, J);
    dwc_kernel<<<K2_BLOCKS, K2_THREADS>>>((float*)d_out);
}